// round 3
// baseline (speedup 1.0000x reference)
#include <cuda_runtime.h>
#include <math.h>

#define PI_F 3.14159265358979323846f

#define Bb   2
#define Cc   128
#define Hh   128
#define Ww   256
#define HW   32768          // Hh*Ww
#define AUXC 133
#define KWF  129            // rfft width bins

// ---------------- static scratch (no allocations allowed) ----------------
__device__ float2 g_R[Bb*KWF*Cc*Hh];      // row-FFT result, layout [b][kw][c][m]
__device__ float  g_feh[Bb*Hh*KWF];       // |FFT| channel-mean, [b][kh][kw]
__device__ float  g_fe[Bb*HW];            // resized freq energy [b][h][w]
__device__ float  g_aux[Bb*AUXC*HW];      // concat(x, coord4, fe)
__device__ float  g_off[Bb*18*HW];        // offset conv output
__device__ float  g_gbuf[Bb*66*HW];       // gate hidden
__device__ float  g_gate[Bb*HW];          // sigmoid gate
__device__ float  g_ybase[Bb*Cc*HW];      // base conv output
__device__ float  g_xT[Bb*HW*Cc];         // x in NHWC for vector gathers
__device__ float  g_wP[9*Cc*Cc];          // def_w permuted to [kk*128+ci][co]

// ---------------- FFT over W (256-pt, real input, keep bins 0..128) ------
__global__ void fft_rows_k(const float* __restrict__ x) {
    __shared__ float2 sm[256];
    __shared__ float2 tw[128];
    int bid = blockIdx.x;
    int m = bid & (Hh-1);
    int c = (bid >> 7) & (Cc-1);
    int b = bid >> 14;
    int tid = threadIdx.x;
    float ang = -2.0f * PI_F * (float)tid / 256.0f;
    tw[tid] = make_float2(cosf(ang), sinf(ang));
    const float* row = x + ((size_t)(b*Cc + c)*Hh + m)*Ww;
    for (int i = tid; i < 256; i += 128) {
        int r = __brev(i) >> 24;
        sm[r] = make_float2(row[i], 0.0f);
    }
    __syncthreads();
#pragma unroll
    for (int s = 1; s <= 8; s++) {
        int half = 1 << (s-1);
        int pos = tid & (half-1);
        int i0 = ((tid >> (s-1)) << s) | pos;
        int i1 = i0 + half;
        float2 w = tw[pos << (8-s)];
        float2 a = sm[i0], bv = sm[i1];
        float2 t = make_float2(bv.x*w.x - bv.y*w.y, bv.x*w.y + bv.y*w.x);
        sm[i0] = make_float2(a.x + t.x, a.y + t.y);
        sm[i1] = make_float2(a.x - t.x, a.y - t.y);
        __syncthreads();
    }
    g_R[((size_t)(b*KWF + tid)*Cc + c)*Hh + m] = sm[tid];
    if (tid == 0)
        g_R[((size_t)(b*KWF + 128)*Cc + c)*Hh + m] = sm[128];
}

// ---------------- FFT over H (128-pt complex) + |.| mean over channels ---
__global__ void fft_cols_k(void) {
    __shared__ float2 sm[128];
    __shared__ float2 tw[64];
    int bid = blockIdx.x;
    int kw = bid % KWF;
    int b  = bid / KWF;
    int tid = threadIdx.x;
    if (tid < 64) {
        float ang = -2.0f * PI_F * (float)tid / 128.0f;
        tw[tid] = make_float2(cosf(ang), sinf(ang));
    }
    float acc = 0.0f;
    const float2* base = g_R + (size_t)(b*KWF + kw)*Cc*Hh;
    for (int c = 0; c < Cc; c++) {
        float2 v = base[c*Hh + tid];
        __syncthreads();                 // protect sm from previous iteration's readers
        sm[__brev(tid) >> 25] = v;
        __syncthreads();
#pragma unroll
        for (int s = 1; s <= 7; s++) {
            if (tid < 64) {
                int half = 1 << (s-1);
                int pos = tid & (half-1);
                int i0 = ((tid >> (s-1)) << s) | pos;
                int i1 = i0 + half;
                float2 w = tw[pos << (7-s)];
                float2 a = sm[i0], bv = sm[i1];
                float2 t = make_float2(bv.x*w.x - bv.y*w.y, bv.x*w.y + bv.y*w.x);
                sm[i0] = make_float2(a.x + t.x, a.y + t.y);
                sm[i1] = make_float2(a.x - t.x, a.y - t.y);
            }
            __syncthreads();
        }
        float2 X = sm[tid];
        acc += sqrtf(X.x*X.x + X.y*X.y);
    }
    float scale = 1.0f / (128.0f * sqrtf((float)(Hh*Ww)));   // mean over C, ortho norm
    g_feh[(size_t)(b*Hh + tid)*KWF + kw] = acc * scale;
}

// ---------------- bilinear width resize 129 -> 256 (half-pixel, clamp) ---
__global__ void resize_fe_k(void) {
    int idx = blockIdx.x*blockDim.x + threadIdx.x;
    if (idx >= Bb*HW) return;
    int w = idx & (Ww-1);
    int h = (idx >> 8) & (Hh-1);
    int b = idx >> 15;
    float px = ((float)w + 0.5f) * (129.0f/256.0f) - 0.5f;
    float x0f = floorf(px);
    float f = px - x0f;
    int x0 = (int)x0f;
    int x1 = x0 + 1;
    x0 = min(max(x0, 0), 128);
    x1 = min(max(x1, 0), 128);
    const float* r = g_feh + (size_t)(b*Hh + h)*KWF;
    g_fe[idx] = r[x0]*(1.0f-f) + r[x1]*f;
}

// ---------------- aux = concat(x, sin/cos coords, fe) --------------------
__global__ void build_aux_k(const float* __restrict__ x) {
    int idx = blockIdx.x*blockDim.x + threadIdx.x;
    if (idx >= Bb*AUXC*HW) return;
    int w  = idx & (Ww-1);
    int h  = (idx >> 8) & (Hh-1);
    int ci = (idx / HW) % AUXC;
    int b  = idx / (AUXC*HW);
    float v;
    if (ci < Cc) {
        v = x[((size_t)(b*Cc + ci)*Hh + h)*Ww + w];
    } else if (ci == Cc) {
        float th = -PI_F + (2.0f*PI_F/255.0f)*(float)w; v = sinf(th);
    } else if (ci == Cc+1) {
        float th = -PI_F + (2.0f*PI_F/255.0f)*(float)w; v = cosf(th);
    } else if (ci == Cc+2) {
        float ph = -0.5f*PI_F + (PI_F/127.0f)*(float)h; v = sinf(ph);
    } else if (ci == Cc+3) {
        float ph = -0.5f*PI_F + (PI_F/127.0f)*(float)h; v = cosf(ph);
    } else {
        v = g_fe[(size_t)b*HW + h*Ww + w];
    }
    g_aux[idx] = v;
}

// ---------------- NCHW -> NHWC transpose of x ----------------------------
__global__ void transpose_k(const float* __restrict__ x) {
    __shared__ float t[32][33];
    int b  = blockIdx.z;
    int p0 = blockIdx.x * 32;   // hw
    int c0 = blockIdx.y * 32;   // channel
    int tx = threadIdx.x, ty = threadIdx.y;
#pragma unroll
    for (int j = 0; j < 4; j++)
        t[ty + j*8][tx] = x[(size_t)(b*Cc + c0 + ty + j*8)*HW + p0 + tx];
    __syncthreads();
#pragma unroll
    for (int j = 0; j < 4; j++)
        g_xT[(size_t)(b*HW + p0 + ty + j*8)*Cc + c0 + tx] = t[tx][ty + j*8];
}

// ---------------- def_w (co,ci,kk) -> wP[kk*128+ci][co] ------------------
__global__ void permw_k(const float* __restrict__ dw) {
    int idx = blockIdx.x*blockDim.x + threadIdx.x;
    if (idx >= 9*Cc*Cc) return;
    int co = idx & 127;
    int ci = (idx >> 7) & 127;
    int kk = idx >> 14;
    g_wP[idx] = dw[(size_t)(co*Cc + ci)*9 + kk];
}

// ---------------- direct 3x3 conv, pad 1, NCHW ---------------------------
// block: 32 couts x (32w x 4h) pixels; thread: 4 couts x 4 rows
// IN_SEL: 0 = g_aux, 1 = external pointer (x)
// OUT_SEL: 0 = g_off, 1 = g_gbuf, 2 = g_ybase
template<int IN_SEL, int OUT_SEL, int CIN, int COUT, int RELU>
__global__ void __launch_bounds__(256) conv3x3_t(
        const float* __restrict__ xin, const float* __restrict__ wgt,
        const float* __restrict__ bias) {
    const float* in = (IN_SEL == 0) ? g_aux : xin;
    float* out = (OUT_SEL == 0) ? g_off : (OUT_SEL == 1) ? g_gbuf : g_ybase;
    __shared__ float tile[6][34];
    __shared__ float ws[32][9];
    int tid = threadIdx.x;
    int xt = tid & 31;
    int ct = tid >> 5;
    int x0 = blockIdx.x * 32;
    int y0 = blockIdx.y * 4;
    const int nCoBlk = (COUT + 31) >> 5;
    int b   = blockIdx.z / nCoBlk;
    int coB = (blockIdx.z % nCoBlk) * 32;
    float acc[4][4];
#pragma unroll
    for (int j = 0; j < 4; j++)
#pragma unroll
        for (int y = 0; y < 4; y++) acc[j][y] = 0.0f;

    for (int ci = 0; ci < CIN; ci++) {
        const float* ip = in + (size_t)(b*CIN + ci)*HW;
        if (tid < 204) {
            int r = tid / 34, cc = tid % 34;
            int gy = y0 + r - 1, gx = x0 + cc - 1;
            float v = 0.0f;
            if (gy >= 0 && gy < Hh && gx >= 0 && gx < Ww) v = ip[gy*Ww + gx];
            tile[r][cc] = v;
        }
        for (int i = tid; i < 288; i += 256) {
            int co = i / 9, tap = i % 9;
            int gco = coB + co;
            ws[co][tap] = (gco < COUT) ? wgt[(size_t)(gco*CIN + ci)*9 + tap] : 0.0f;
        }
        __syncthreads();
        float v[6][3];
#pragma unroll
        for (int r = 0; r < 6; r++)
#pragma unroll
            for (int k = 0; k < 3; k++) v[r][k] = tile[r][xt + k];
#pragma unroll
        for (int j = 0; j < 4; j++) {
            float wr[9];
#pragma unroll
            for (int t = 0; t < 9; t++) wr[t] = ws[ct*4 + j][t];
#pragma unroll
            for (int y = 0; y < 4; y++) {
                float s = acc[j][y];
                s = fmaf(v[y  ][0], wr[0], s); s = fmaf(v[y  ][1], wr[1], s); s = fmaf(v[y  ][2], wr[2], s);
                s = fmaf(v[y+1][0], wr[3], s); s = fmaf(v[y+1][1], wr[4], s); s = fmaf(v[y+1][2], wr[5], s);
                s = fmaf(v[y+2][0], wr[6], s); s = fmaf(v[y+2][1], wr[7], s); s = fmaf(v[y+2][2], wr[8], s);
                acc[j][y] = s;
            }
        }
        __syncthreads();
    }
#pragma unroll
    for (int j = 0; j < 4; j++) {
        int co = coB + ct*4 + j;
        if (co < COUT) {
            float bs = bias[co];
#pragma unroll
            for (int y = 0; y < 4; y++) {
                float o = acc[j][y] + bs;
                if (RELU) o = fmaxf(o, 0.0f);
                out[((size_t)(b*COUT + co)*Hh + y0 + y)*Ww + x0 + xt] = o;
            }
        }
    }
}

// ---------------- 1x1 gate conv + sigmoid --------------------------------
__global__ void gate1x1_k(const float* __restrict__ w2, const float* __restrict__ b2) {
    int idx = blockIdx.x*blockDim.x + threadIdx.x;
    if (idx >= Bb*HW) return;
    int b = idx >> 15;
    int p = idx & (HW-1);
    float s = b2[0];
#pragma unroll 6
    for (int c = 0; c < 66; c++)
        s = fmaf(g_gbuf[(size_t)(b*66 + c)*HW + p], w2[c], s);
    g_gate[idx] = 1.0f / (1.0f + expf(-s));
}

// ---------------- fused deform-sample + 1x1 (K=1152 GEMM) + blend --------
// block: 128 couts x 128 pixels; thread: 8x8 register tile
__global__ void __launch_bounds__(256) deform_gemm_k(
        const float* __restrict__ defb, float* __restrict__ out) {
    __shared__ float Ssm[32][128];
    __shared__ float Wsm[32][128];
    __shared__ int   mX0[128], mY0[128];
    __shared__ float mFx[128], mFy[128];
    int tid = threadIdx.x;
    int blk = blockIdx.x;
    int b    = blk >> 8;                 // 256 pixel-blocks per batch
    int pix0 = (blk & 255) * 128;
    int coIdx = (tid & 15) * 8;
    int pxIdx = (tid >> 4) * 8;
    float acc[8][8];
#pragma unroll
    for (int i = 0; i < 8; i++)
#pragma unroll
        for (int j = 0; j < 8; j++) acc[i][j] = 0.0f;
    int p = tid >> 1, sub = tid & 1;

#pragma unroll 1
    for (int kk = 0; kk < 9; kk++) {
        __syncthreads();
        if (tid < 128) {
            int pp = pix0 + tid;
            int hh = pp >> 8, ww = pp & (Ww-1);
            float ox = g_off[(size_t)(b*18 + 2*kk    )*HW + pp];
            float oy = g_off[(size_t)(b*18 + 2*kk + 1)*HW + pp];
            float fpx = (float)ww + ox;
            float fpy = (float)hh + oy;
            float fx0 = floorf(fpx), fy0 = floorf(fpy);
            mX0[tid] = (int)fx0;  mY0[tid] = (int)fy0;
            mFx[tid] = fpx - fx0; mFy[tid] = fpy - fy0;
        }
        __syncthreads();
        int X0 = mX0[p], Y0 = mY0[p];
        float fx = mFx[p], fy = mFy[p];
        float w00 = (1.0f-fx)*(1.0f-fy), w10 = fx*(1.0f-fy);
        float w01 = (1.0f-fx)*fy,        w11 = fx*fy;
        if (X0   < 0 || X0   >= Ww) { w00 = 0.0f; w01 = 0.0f; }
        if (X0+1 < 0 || X0+1 >= Ww) { w10 = 0.0f; w11 = 0.0f; }
        if (Y0   < 0 || Y0   >= Hh) { w00 = 0.0f; w10 = 0.0f; }
        if (Y0+1 < 0 || Y0+1 >= Hh) { w01 = 0.0f; w11 = 0.0f; }
        int cx0 = min(max(X0,   0), Ww-1), cx1 = min(max(X0+1, 0), Ww-1);
        int cy0 = min(max(Y0,   0), Hh-1), cy1 = min(max(Y0+1, 0), Hh-1);
        const float4* p00 = (const float4*)(g_xT + ((size_t)(b*Hh + cy0)*Ww + cx0)*Cc);
        const float4* p10 = (const float4*)(g_xT + ((size_t)(b*Hh + cy0)*Ww + cx1)*Cc);
        const float4* p01 = (const float4*)(g_xT + ((size_t)(b*Hh + cy1)*Ww + cx0)*Cc);
        const float4* p11 = (const float4*)(g_xT + ((size_t)(b*Hh + cy1)*Ww + cx1)*Cc);

#pragma unroll 1
        for (int cc = 0; cc < 4; cc++) {
            __syncthreads();
            int cb  = sub * 16;             // within-chunk ci
            int cig = cc*32 + cb;           // global ci
#pragma unroll
            for (int q = 0; q < 4; q++) {
                int f4 = (cig >> 2) + q;
                float4 a00 = p00[f4], a10 = p10[f4], a01 = p01[f4], a11 = p11[f4];
                float4 r;
                r.x = w00*a00.x + w10*a10.x + w01*a01.x + w11*a11.x;
                r.y = w00*a00.y + w10*a10.y + w01*a01.y + w11*a11.y;
                r.z = w00*a00.z + w10*a10.z + w01*a01.z + w11*a11.z;
                r.w = w00*a00.w + w10*a10.w + w01*a01.w + w11*a11.w;
                Ssm[cb + q*4 + 0][p] = r.x;
                Ssm[cb + q*4 + 1][p] = r.y;
                Ssm[cb + q*4 + 2][p] = r.z;
                Ssm[cb + q*4 + 3][p] = r.w;
            }
            int krow0 = kk*128 + cc*32;
            for (int i = tid; i < 32*128; i += 256) {
                int kq = i >> 7, co = i & 127;
                Wsm[kq][co] = g_wP[(size_t)(krow0 + kq)*Cc + co];
            }
            __syncthreads();
#pragma unroll 8
            for (int kq = 0; kq < 32; kq++) {
                float4 a0 = *(const float4*)&Wsm[kq][coIdx];
                float4 a1 = *(const float4*)&Wsm[kq][coIdx+4];
                float4 b0 = *(const float4*)&Ssm[kq][pxIdx];
                float4 b1 = *(const float4*)&Ssm[kq][pxIdx+4];
                float av[8] = {a0.x,a0.y,a0.z,a0.w,a1.x,a1.y,a1.z,a1.w};
                float bv[8] = {b0.x,b0.y,b0.z,b0.w,b1.x,b1.y,b1.z,b1.w};
#pragma unroll
                for (int i = 0; i < 8; i++)
#pragma unroll
                    for (int j = 0; j < 8; j++)
                        acc[i][j] = fmaf(av[i], bv[j], acc[i][j]);
            }
        }
    }
    // epilogue: out = (1-gate)*y_base + gate*(y_def + bias)
    int pixg = pix0 + pxIdx;
    float gt[8];
#pragma unroll
    for (int j = 0; j < 8; j++) gt[j] = g_gate[(size_t)b*HW + pixg + j];
#pragma unroll
    for (int i = 0; i < 8; i++) {
        int co = coIdx + i;
        float bs = defb[co];
        const float* yb = g_ybase + (size_t)(b*Cc + co)*HW + pixg;
        float* op = out + (size_t)(b*Cc + co)*HW + pixg;
#pragma unroll
        for (int j = 0; j < 8; j++) {
            float yd = acc[i][j] + bs;
            op[j] = (1.0f - gt[j])*yb[j] + gt[j]*yd;
        }
    }
}

// ---------------- host launcher ------------------------------------------
extern "C" void kernel_launch(void* const* d_in, const int* in_sizes, int n_in,
                              void* d_out, int out_size) {
    const float* x      = (const float*)d_in[0];
    const float* off_w  = (const float*)d_in[1];
    const float* off_b  = (const float*)d_in[2];
    const float* gw1    = (const float*)d_in[3];
    const float* gb1    = (const float*)d_in[4];
    const float* gw2    = (const float*)d_in[5];
    const float* gb2    = (const float*)d_in[6];
    const float* base_w = (const float*)d_in[7];
    const float* base_b = (const float*)d_in[8];
    const float* def_w  = (const float*)d_in[9];
    const float* def_b  = (const float*)d_in[10];
    float* out = (float*)d_out;

    fft_rows_k<<<Bb*Cc*Hh, 128>>>(x);
    fft_cols_k<<<Bb*KWF, 128>>>();
    resize_fe_k<<<(Bb*HW + 255)/256, 256>>>();
    build_aux_k<<<(Bb*AUXC*HW + 255)/256, 256>>>(x);
    transpose_k<<<dim3(HW/32, Cc/32, Bb), dim3(32, 8)>>>(x);
    permw_k<<<(9*Cc*Cc + 255)/256, 256>>>(def_w);

    conv3x3_t<0, 0, AUXC, 18, 0><<<dim3(8, 32, Bb*1), 256>>>(nullptr, off_w, off_b);
    conv3x3_t<0, 1, AUXC, 66, 1><<<dim3(8, 32, Bb*3), 256>>>(nullptr, gw1, gb1);
    conv3x3_t<1, 2, Cc,  Cc,  0><<<dim3(8, 32, Bb*4), 256>>>(x, base_w, base_b);
    gate1x1_k<<<(Bb*HW + 255)/256, 256>>>(gw2, gb2);
    deform_gemm_k<<<Bb*(HW/128), 256>>>(def_b, out);
}